// round 5
// baseline (speedup 1.0000x reference)
#include <cuda_runtime.h>
#include <math.h>

// Problem constants
#define Dm   1024
#define Tm   2048
#define Bbm  2
#define Hm   16
#define DHm  64
#define Rm   8
#define Mtot (Bbm * Tm)   // 4096 rows

// ---------------------------------------------------------------------------
// Scratch (device globals — no allocation allowed)
// ---------------------------------------------------------------------------
__device__ float g_wq_eff[Dm * Dm];
__device__ float g_wv_eff[Dm * Dm];
__device__ float g_q[Mtot * Dm];
__device__ float g_k[Mtot * Dm];
__device__ float g_v[Mtot * Dm];
__device__ float g_o[Mtot * Dm];

// ---------------------------------------------------------------------------
// 1) Fold LoRA into effective weights: W_eff[i,k] = w[i,k] + 2 * sum_r B[i,r]*A[r,k]
// ---------------------------------------------------------------------------
__global__ __launch_bounds__(256) void eff_weight_kernel(
    const float* __restrict__ wq_w, const float* __restrict__ wq_A, const float* __restrict__ wq_B,
    const float* __restrict__ wv_w, const float* __restrict__ wv_A, const float* __restrict__ wv_B)
{
    const float* w; const float* A; const float* Bp; float* out;
    if (blockIdx.z == 0) { w = wq_w; A = wq_A; Bp = wq_B; out = g_wq_eff; }
    else                 { w = wv_w; A = wv_A; Bp = wv_B; out = g_wv_eff; }
    int idx = blockIdx.x * 256 + threadIdx.x;     // over Dm*Dm
    int i = idx >> 10;
    int j = idx & 1023;
    float acc = 0.f;
#pragma unroll
    for (int r = 0; r < Rm; r++) acc += Bp[i * Rm + r] * A[r * Dm + j];
    out[idx] = w[idx] + 2.0f * acc;
}

// ---------------------------------------------------------------------------
// SGEMM core: C[M,1024] = A[M,1024] @ B[1024,1024]^T   (both operands K-major)
// 128x128 block tile, BK=8, 256 threads, 8x8 per-thread microtile.
// ---------------------------------------------------------------------------
__device__ __forceinline__ void gemm_core_1024(
    const float* __restrict__ A, const float* __restrict__ B, float* __restrict__ C)
{
    __shared__ float As[8][128];
    __shared__ float Bs[8][128];
    const int tid = threadIdx.x;
    const int tx = tid & 15, ty = tid >> 4;
    const int rowBlock = blockIdx.y * 128;
    const int colBlock = blockIdx.x * 128;
    const int loadRow = tid >> 1;          // 0..127
    const int loadCol = (tid & 1) * 4;     // 0 or 4
    const float* Ap = A + (size_t)(rowBlock + loadRow) * 1024 + loadCol;
    const float* Bp = B + (size_t)(colBlock + loadRow) * 1024 + loadCol;

    float acc[8][8] = {};
    for (int k0 = 0; k0 < 1024; k0 += 8) {
        float4 a4 = *reinterpret_cast<const float4*>(Ap + k0);
        float4 b4 = *reinterpret_cast<const float4*>(Bp + k0);
        As[loadCol + 0][loadRow] = a4.x; As[loadCol + 1][loadRow] = a4.y;
        As[loadCol + 2][loadRow] = a4.z; As[loadCol + 3][loadRow] = a4.w;
        Bs[loadCol + 0][loadRow] = b4.x; Bs[loadCol + 1][loadRow] = b4.y;
        Bs[loadCol + 2][loadRow] = b4.z; Bs[loadCol + 3][loadRow] = b4.w;
        __syncthreads();
#pragma unroll
        for (int kk = 0; kk < 8; kk++) {
            float4 a04 = *reinterpret_cast<const float4*>(&As[kk][ty * 8]);
            float4 a14 = *reinterpret_cast<const float4*>(&As[kk][ty * 8 + 4]);
            float4 b04 = *reinterpret_cast<const float4*>(&Bs[kk][tx * 8]);
            float4 b14 = *reinterpret_cast<const float4*>(&Bs[kk][tx * 8 + 4]);
            float a[8]  = {a04.x, a04.y, a04.z, a04.w, a14.x, a14.y, a14.z, a14.w};
            float bb[8] = {b04.x, b04.y, b04.z, b04.w, b14.x, b14.y, b14.z, b14.w};
#pragma unroll
            for (int i = 0; i < 8; i++)
#pragma unroll
                for (int j = 0; j < 8; j++)
                    acc[i][j] += a[i] * bb[j];
        }
        __syncthreads();
    }
#pragma unroll
    for (int i = 0; i < 8; i++) {
        float* cr = C + (size_t)(rowBlock + ty * 8 + i) * 1024 + colBlock + tx * 8;
        *reinterpret_cast<float4*>(cr)     = make_float4(acc[i][0], acc[i][1], acc[i][2], acc[i][3]);
        *reinterpret_cast<float4*>(cr + 4) = make_float4(acc[i][4], acc[i][5], acc[i][6], acc[i][7]);
    }
}

// 2) Q/K/V projections fused over grid.z
__global__ __launch_bounds__(256) void qkv_gemm_kernel(
    const float* __restrict__ x, const float* __restrict__ wk_w)
{
    const float* W; float* C;
    if (blockIdx.z == 0)      { W = g_wq_eff; C = g_q; }
    else if (blockIdx.z == 1) { W = wk_w;     C = g_k; }
    else                      { W = g_wv_eff; C = g_v; }
    gemm_core_1024(x, W, C);
}

// 4) Output projection: out = attn_out @ wo^T
__global__ __launch_bounds__(256) void out_gemm_kernel(
    const float* __restrict__ wo_w, float* __restrict__ out)
{
    gemm_core_1024(g_o, wo_w, out);
}

// ---------------------------------------------------------------------------
// 3) Causal flash attention. One block = 64 queries of one (b,h).
//    256 threads, 16x16 thread grid, 4x4 microtiles. Online softmax.
// ---------------------------------------------------------------------------
#define BQ   64
#define BKV  64
#define SROW 68   // stride pad; 68 floats = 272B, multiple of 16B -> float4 ok

__global__ __launch_bounds__(256) void flash_kernel()
{
    extern __shared__ float sh[];
    float (*sQ)[SROW]  = (float (*)[SROW])(sh);
    float (*sKt)[SROW] = (float (*)[SROW])(sh + BQ * SROW);       // [d][key]
    float (*sV)[SROW]  = (float (*)[SROW])(sh + 2 * BQ * SROW);   // [key][d]
    float (*sP)[SROW]  = (float (*)[SROW])(sh + 3 * BQ * SROW);   // [query][key]

    const int tid = threadIdx.x;
    const int tx = tid & 15, ty = tid >> 4;
    const int bh = blockIdx.y;            // 0..31
    const int b = bh >> 4, h = bh & 15;
    const int qt = blockIdx.x;
    const int q0 = qt * BQ;
    const size_t baseRow = (size_t)b * Tm;
    const int headOff = h * DHm;

    // Load Q tile [64][64]
    for (int i = tid; i < BQ * (DHm / 4); i += 256) {
        int r  = i >> 4;
        int d4 = (i & 15) << 2;
        float4 v = *reinterpret_cast<const float4*>(
            &g_q[(baseRow + q0 + r) * Dm + headOff + d4]);
        *reinterpret_cast<float4*>(&sQ[r][d4]) = v;
    }

    const int r0 = ty * 4, c0 = tx * 4;
    float m_i[4], l_i[4], Oacc[4][4];
#pragma unroll
    for (int i = 0; i < 4; i++) {
        m_i[i] = -1e30f; l_i[i] = 0.f;
#pragma unroll
        for (int j = 0; j < 4; j++) Oacc[i][j] = 0.f;
    }

    for (int kt = 0; kt <= qt; kt++) {
        const int k0 = kt * BKV;
        __syncthreads();   // prior-iter reads done (also covers sQ stores on iter 0)

        // Load K tile transposed -> sKt[d][key], V tile -> sV[key][d]
        for (int i = tid; i < BKV * (DHm / 4); i += 256) {
            int r  = i >> 4;
            int d4 = (i & 15) << 2;
            float4 kv = *reinterpret_cast<const float4*>(
                &g_k[(baseRow + k0 + r) * Dm + headOff + d4]);
            sKt[d4 + 0][r] = kv.x; sKt[d4 + 1][r] = kv.y;
            sKt[d4 + 2][r] = kv.z; sKt[d4 + 3][r] = kv.w;
            float4 vv = *reinterpret_cast<const float4*>(
                &g_v[(baseRow + k0 + r) * Dm + headOff + d4]);
            *reinterpret_cast<float4*>(&sV[r][d4]) = vv;
        }
        __syncthreads();

        // S = Q K^T (4x4 per thread)
        float S[4][4] = {};
#pragma unroll 4
        for (int d = 0; d < DHm; d++) {
            float qr[4];
#pragma unroll
            for (int i = 0; i < 4; i++) qr[i] = sQ[r0 + i][d];
            float4 kr = *reinterpret_cast<const float4*>(&sKt[d][c0]);
            float kk[4] = {kr.x, kr.y, kr.z, kr.w};
#pragma unroll
            for (int i = 0; i < 4; i++)
#pragma unroll
                for (int j = 0; j < 4; j++)
                    S[i][j] += qr[i] * kk[j];
        }
        const bool diag = (kt == qt);
#pragma unroll
        for (int i = 0; i < 4; i++)
#pragma unroll
            for (int j = 0; j < 4; j++) {
                float s = S[i][j] * 0.125f;                 // 1/sqrt(64)
                if (diag && (k0 + c0 + j > q0 + r0 + i)) s = -1e30f;
                S[i][j] = s;
            }

        // Online softmax (row groups of 16 lanes; tid layout keeps xor<16 in-warp)
#pragma unroll
        for (int i = 0; i < 4; i++) {
            float mx = fmaxf(fmaxf(S[i][0], S[i][1]), fmaxf(S[i][2], S[i][3]));
#pragma unroll
            for (int o = 1; o < 16; o <<= 1) mx = fmaxf(mx, __shfl_xor_sync(0xffffffffu, mx, o));
            float mnew = fmaxf(m_i[i], mx);
            float corr = __expf(m_i[i] - mnew);
            float rs = 0.f;
#pragma unroll
            for (int j = 0; j < 4; j++) { float p = __expf(S[i][j] - mnew); S[i][j] = p; rs += p; }
#pragma unroll
            for (int o = 1; o < 16; o <<= 1) rs += __shfl_xor_sync(0xffffffffu, rs, o);
            l_i[i] = l_i[i] * corr + rs;
            m_i[i] = mnew;
#pragma unroll
            for (int j = 0; j < 4; j++) Oacc[i][j] *= corr;
            *reinterpret_cast<float4*>(&sP[r0 + i][c0]) =
                make_float4(S[i][0], S[i][1], S[i][2], S[i][3]);
        }
        __syncthreads();

        // Oacc += P @ V
#pragma unroll 4
        for (int jj = 0; jj < BKV; jj++) {
            float pr[4];
#pragma unroll
            for (int i = 0; i < 4; i++) pr[i] = sP[r0 + i][jj];
            float4 vr = *reinterpret_cast<const float4*>(&sV[jj][c0]);
            float vv[4] = {vr.x, vr.y, vr.z, vr.w};
#pragma unroll
            for (int i = 0; i < 4; i++)
#pragma unroll
                for (int j = 0; j < 4; j++)
                    Oacc[i][j] += pr[i] * vv[j];
        }
    }

    // Normalize and write out (in [B*T, D] layout for the final GEMM)
#pragma unroll
    for (int i = 0; i < 4; i++) {
        float inv = 1.0f / l_i[i];
        *reinterpret_cast<float4*>(&g_o[(baseRow + q0 + r0 + i) * Dm + headOff + c0]) =
            make_float4(Oacc[i][0] * inv, Oacc[i][1] * inv, Oacc[i][2] * inv, Oacc[i][3] * inv);
    }
}

// ---------------------------------------------------------------------------
// Launch
// ---------------------------------------------------------------------------
extern "C" void kernel_launch(void* const* d_in, const int* in_sizes, int n_in,
                              void* d_out, int out_size)
{
    const float* x    = (const float*)d_in[0];
    // d_in[1] = attn_mask (statically causal triu(k=1) -> implemented directly)
    const float* wq_w = (const float*)d_in[2];
    const float* wq_A = (const float*)d_in[3];
    const float* wq_B = (const float*)d_in[4];
    const float* wk_w = (const float*)d_in[5];
    const float* wv_w = (const float*)d_in[6];
    const float* wv_A = (const float*)d_in[7];
    const float* wv_B = (const float*)d_in[8];
    const float* wo_w = (const float*)d_in[9];
    float* out = (float*)d_out;

    // 1) LoRA fold
    eff_weight_kernel<<<dim3((Dm * Dm) / 256, 1, 2), 256>>>(wq_w, wq_A, wq_B,
                                                            wv_w, wv_A, wv_B);
    // 2) Q/K/V projections
    qkv_gemm_kernel<<<dim3(8, 32, 3), 256>>>(x, wk_w);

    // 3) Flash attention
    int smem_bytes = 4 * BQ * SROW * (int)sizeof(float);   // 69632 B
    cudaFuncSetAttribute(flash_kernel,
                         cudaFuncAttributeMaxDynamicSharedMemorySize, smem_bytes);
    flash_kernel<<<dim3(Tm / BQ, Bbm * Hm), 256, smem_bytes>>>();

    // 4) Output projection -> d_out
    out_gemm_kernel<<<dim3(8, 32, 1), 256>>>(wo_w, out);
}

// round 6
// speedup vs baseline: 2.9283x; 2.9283x over previous
#include <cuda_runtime.h>
#include <math.h>
#include <stdint.h>

// Problem constants
#define Dm   1024
#define Tm   2048
#define Bbm  2
#define Hm   16
#define DHm  64
#define Rm   8
#define Mtot (Bbm * Tm)   // 4096 rows

// ---------------------------------------------------------------------------
// Scratch (device globals — no allocation allowed)
// ---------------------------------------------------------------------------
__device__ float g_wq_eff[Dm * Dm];
__device__ float g_wv_eff[Dm * Dm];
__device__ float g_q[Mtot * Dm];
__device__ float g_k[Mtot * Dm];
__device__ float g_v[Mtot * Dm];
__device__ float g_o[Mtot * Dm];

// ---------------------------------------------------------------------------
// tf32 helpers
// ---------------------------------------------------------------------------
__device__ __forceinline__ float tf32r(float x) {
    uint32_t y;
    asm("cvt.rna.tf32.f32 %0, %1;" : "=r"(y) : "f"(x));
    return __uint_as_float(y);
}

// D += A*B, m16n8k8 tf32, A row-major, B col-major, fp32 accumulate
__device__ __forceinline__ void mma_tf32(float* c, const float* a, float b0f, float b1f) {
    uint32_t a0 = __float_as_uint(a[0]);
    uint32_t a1 = __float_as_uint(a[1]);
    uint32_t a2 = __float_as_uint(a[2]);
    uint32_t a3 = __float_as_uint(a[3]);
    uint32_t b0 = __float_as_uint(b0f);
    uint32_t b1 = __float_as_uint(b1f);
    asm volatile(
        "mma.sync.aligned.m16n8k8.row.col.f32.tf32.tf32.f32 "
        "{%0,%1,%2,%3}, {%4,%5,%6,%7}, {%8,%9}, {%0,%1,%2,%3};\n"
        : "+f"(c[0]), "+f"(c[1]), "+f"(c[2]), "+f"(c[3])
        : "r"(a0), "r"(a1), "r"(a2), "r"(a3), "r"(b0), "r"(b1));
}

// ---------------------------------------------------------------------------
// 1) Fold LoRA into effective weights: W_eff[i,k] = w[i,k] + 2 * sum_r B[i,r]*A[r,k]
// ---------------------------------------------------------------------------
__global__ __launch_bounds__(256) void eff_weight_kernel(
    const float* __restrict__ wq_w, const float* __restrict__ wq_A, const float* __restrict__ wq_B,
    const float* __restrict__ wv_w, const float* __restrict__ wv_A, const float* __restrict__ wv_B)
{
    const float* w; const float* A; const float* Bp; float* out;
    if (blockIdx.z == 0) { w = wq_w; A = wq_A; Bp = wq_B; out = g_wq_eff; }
    else                 { w = wv_w; A = wv_A; Bp = wv_B; out = g_wv_eff; }
    int idx = blockIdx.x * 256 + threadIdx.x;     // over Dm*Dm
    int i = idx >> 10;
    int j = idx & 1023;
    float acc = 0.f;
#pragma unroll
    for (int r = 0; r < Rm; r++) acc += Bp[i * Rm + r] * A[r * Dm + j];
    out[idx] = w[idx] + 2.0f * acc;
}

// ---------------------------------------------------------------------------
// tf32 tensor-core GEMM: C[M,1024] = A[M,1024] @ W[1024,1024]^T
// 128x128 block tile, BK=16, 256 threads = 8 warps (2m x 4n), warp tile 64x32.
// Register-prefetch of the next K-stage overlaps global latency with MMAs.
// smem stride 20 floats -> conflict-free fragment loads ((20g+t) distinct mod 32).
// ---------------------------------------------------------------------------
#define GST 20

__device__ __forceinline__ void gemm_tf32_core(
    const float* __restrict__ A, const float* __restrict__ W, float* __restrict__ C)
{
    __shared__ float As[128][GST];
    __shared__ float Bs[128][GST];

    const int tid  = threadIdx.x;
    const int warp = tid >> 5, lane = tid & 31;
    const int g = lane >> 2, t = lane & 3;
    const int wm = warp & 1;       // 0..1  -> 64 rows each
    const int wn = warp >> 1;      // 0..3  -> 32 cols each
    const int rowBlock = blockIdx.y * 128;
    const int colBlock = blockIdx.x * 128;

    const int lr = tid >> 2;            // 0..63
    const int lc = (tid & 3) << 2;      // 0,4,8,12
    const float* Ap = A + (size_t)(rowBlock + lr) * 1024 + lc;
    const float* Wp = W + (size_t)(colBlock + lr) * 1024 + lc;

    float acc[4][4][4];
#pragma unroll
    for (int i = 0; i < 4; i++)
#pragma unroll
        for (int j = 0; j < 4; j++)
#pragma unroll
            for (int r = 0; r < 4; r++) acc[i][j][r] = 0.f;

    // prefetch stage 0
    float4 pa0 = *(const float4*)(Ap);
    float4 pa1 = *(const float4*)(Ap + (size_t)64 * 1024);
    float4 pb0 = *(const float4*)(Wp);
    float4 pb1 = *(const float4*)(Wp + (size_t)64 * 1024);

    for (int k0 = 0; k0 < 1024; k0 += 16) {
        // store prefetched stage (with tf32 rounding)
        As[lr][lc+0]=tf32r(pa0.x); As[lr][lc+1]=tf32r(pa0.y); As[lr][lc+2]=tf32r(pa0.z); As[lr][lc+3]=tf32r(pa0.w);
        As[lr+64][lc+0]=tf32r(pa1.x); As[lr+64][lc+1]=tf32r(pa1.y); As[lr+64][lc+2]=tf32r(pa1.z); As[lr+64][lc+3]=tf32r(pa1.w);
        Bs[lr][lc+0]=tf32r(pb0.x); Bs[lr][lc+1]=tf32r(pb0.y); Bs[lr][lc+2]=tf32r(pb0.z); Bs[lr][lc+3]=tf32r(pb0.w);
        Bs[lr+64][lc+0]=tf32r(pb1.x); Bs[lr+64][lc+1]=tf32r(pb1.y); Bs[lr+64][lc+2]=tf32r(pb1.z); Bs[lr+64][lc+3]=tf32r(pb1.w);
        __syncthreads();

        if (k0 + 16 < 1024) {   // prefetch next stage (overlaps with MMAs)
            pa0 = *(const float4*)(Ap + k0 + 16);
            pa1 = *(const float4*)(Ap + (size_t)64 * 1024 + k0 + 16);
            pb0 = *(const float4*)(Wp + k0 + 16);
            pb1 = *(const float4*)(Wp + (size_t)64 * 1024 + k0 + 16);
        }

#pragma unroll
        for (int kc = 0; kc < 16; kc += 8) {
            float a[4][4];
#pragma unroll
            for (int mt = 0; mt < 4; mt++) {
                int row = wm * 64 + mt * 16;
                a[mt][0] = As[row + g    ][kc + t];
                a[mt][1] = As[row + g + 8][kc + t];
                a[mt][2] = As[row + g    ][kc + t + 4];
                a[mt][3] = As[row + g + 8][kc + t + 4];
            }
            float b[4][2];
#pragma unroll
            for (int nt = 0; nt < 4; nt++) {
                int col = wn * 32 + nt * 8;
                b[nt][0] = Bs[col + g][kc + t];
                b[nt][1] = Bs[col + g][kc + t + 4];
            }
#pragma unroll
            for (int mt = 0; mt < 4; mt++)
#pragma unroll
                for (int nt = 0; nt < 4; nt++)
                    mma_tf32(acc[mt][nt], a[mt], b[nt][0], b[nt][1]);
        }
        __syncthreads();
    }

    // epilogue: c0,c1 at (row g, cols 2t,2t+1); c2,c3 at row g+8
#pragma unroll
    for (int mt = 0; mt < 4; mt++) {
        int row = rowBlock + wm * 64 + mt * 16 + g;
#pragma unroll
        for (int nt = 0; nt < 4; nt++) {
            int col = colBlock + wn * 32 + nt * 8 + 2 * t;
            *(float2*)&C[(size_t)row * 1024 + col] =
                make_float2(acc[mt][nt][0], acc[mt][nt][1]);
            *(float2*)&C[(size_t)(row + 8) * 1024 + col] =
                make_float2(acc[mt][nt][2], acc[mt][nt][3]);
        }
    }
}

// 2) Q/K/V projections fused over grid.z
__global__ __launch_bounds__(256) void qkv_gemm_kernel(
    const float* __restrict__ x, const float* __restrict__ wk_w)
{
    const float* W; float* C;
    if (blockIdx.z == 0)      { W = g_wq_eff; C = g_q; }
    else if (blockIdx.z == 1) { W = wk_w;     C = g_k; }
    else                      { W = g_wv_eff; C = g_v; }
    gemm_tf32_core(x, W, C);
}

// 4) Output projection: out = attn_out @ wo^T
__global__ __launch_bounds__(256) void out_gemm_kernel(
    const float* __restrict__ wo_w, float* __restrict__ out)
{
    gemm_tf32_core(g_o, wo_w, out);
}

// ---------------------------------------------------------------------------
// 3) Causal flash attention, tensor-core tf32.
//    Block = 64 queries x one (b,h). 128 threads = 4 warps, warp = 16 q-rows.
//    S = Q K^T and O += P V both via mma.m16n8k8.tf32; fp32 online softmax.
//    smem stride 68 floats -> conflict-free K fragment loads.
// ---------------------------------------------------------------------------
#define FST 68

__global__ __launch_bounds__(128) void flash_tf32_kernel()
{
    extern __shared__ float sh[];
    float* sK = sh;                   // [64][FST]
    float* sV = sh + 64 * FST;        // [64][FST]  (V[key][d])
    float* sP = sh + 2 * 64 * FST;    // [64][FST]  (warp-private row bands)

    const int tid  = threadIdx.x;
    const int warp = tid >> 5, lane = tid & 31;
    const int g = lane >> 2, t = lane & 3;
    const int bh = blockIdx.y;             // 0..31
    const int b = bh >> 4, h = bh & 15;
    const int qt = gridDim.x - 1 - blockIdx.x;   // longest tiles first
    const int q0 = qt * 64;
    const size_t baseRow = (size_t)b * Tm;
    const int headOff = h * DHm;

    // ---- stage Q into sK, extract A-fragments into registers ----
    for (int i = tid; i < 64 * 16; i += 128) {
        int r = i >> 4, c4 = (i & 15) << 2;
        float4 v = *(const float4*)&g_q[(baseRow + q0 + r) * Dm + headOff + c4];
        float* d = &sK[r * FST + c4];
        d[0] = tf32r(v.x); d[1] = tf32r(v.y); d[2] = tf32r(v.z); d[3] = tf32r(v.w);
    }
    __syncthreads();
    float qf[8][4];
    {
        const int rb = warp * 16;
#pragma unroll
        for (int kc = 0; kc < 8; kc++) {
            qf[kc][0] = sK[(rb + g    ) * FST + kc * 8 + t];
            qf[kc][1] = sK[(rb + g + 8) * FST + kc * 8 + t];
            qf[kc][2] = sK[(rb + g    ) * FST + kc * 8 + t + 4];
            qf[kc][3] = sK[(rb + g + 8) * FST + kc * 8 + t + 4];
        }
    }
    __syncthreads();

    float m0 = -1e30f, m1 = -1e30f, l0 = 0.f, l1 = 0.f;
    float o[8][4];
#pragma unroll
    for (int nt = 0; nt < 8; nt++)
#pragma unroll
        for (int r = 0; r < 4; r++) o[nt][r] = 0.f;

    const int row0 = q0 + warp * 16 + g;
    const int row1 = row0 + 8;

    for (int kt = 0; kt <= qt; kt++) {
        const int k0 = kt * 64;

        // load K and V tiles (tf32-rounded)
        for (int i = tid; i < 64 * 16; i += 128) {
            int r = i >> 4, c4 = (i & 15) << 2;
            size_t gidx = (baseRow + k0 + r) * Dm + headOff + c4;
            float4 kv = *(const float4*)&g_k[gidx];
            float4 vv = *(const float4*)&g_v[gidx];
            float* dk = &sK[r * FST + c4];
            dk[0] = tf32r(kv.x); dk[1] = tf32r(kv.y); dk[2] = tf32r(kv.z); dk[3] = tf32r(kv.w);
            float* dv = &sV[r * FST + c4];
            dv[0] = tf32r(vv.x); dv[1] = tf32r(vv.y); dv[2] = tf32r(vv.z); dv[3] = tf32r(vv.w);
        }
        __syncthreads();

        // ---- S = Q K^T ----
        float s[8][4];
#pragma unroll
        for (int nt = 0; nt < 8; nt++) {
            s[nt][0] = s[nt][1] = s[nt][2] = s[nt][3] = 0.f;
#pragma unroll
            for (int kc = 0; kc < 8; kc++) {
                float b0 = sK[(nt * 8 + g) * FST + kc * 8 + t];
                float b1 = sK[(nt * 8 + g) * FST + kc * 8 + t + 4];
                mma_tf32(s[nt], qf[kc], b0, b1);
            }
        }

        // ---- scale + causal mask ----
        const bool diag = (kt == qt);
#pragma unroll
        for (int nt = 0; nt < 8; nt++) {
            int c0 = k0 + nt * 8 + 2 * t, c1 = c0 + 1;
            s[nt][0] *= 0.125f; s[nt][1] *= 0.125f;
            s[nt][2] *= 0.125f; s[nt][3] *= 0.125f;
            if (diag) {
                if (c0 > row0) s[nt][0] = -1e30f;
                if (c1 > row0) s[nt][1] = -1e30f;
                if (c0 > row1) s[nt][2] = -1e30f;
                if (c1 > row1) s[nt][3] = -1e30f;
            }
        }

        // ---- online softmax (rows row0, row1 per thread; quad = xor1, xor2) ----
        float mx0 = -1e30f, mx1 = -1e30f;
#pragma unroll
        for (int nt = 0; nt < 8; nt++) {
            mx0 = fmaxf(mx0, fmaxf(s[nt][0], s[nt][1]));
            mx1 = fmaxf(mx1, fmaxf(s[nt][2], s[nt][3]));
        }
        mx0 = fmaxf(mx0, __shfl_xor_sync(0xffffffffu, mx0, 1));
        mx0 = fmaxf(mx0, __shfl_xor_sync(0xffffffffu, mx0, 2));
        mx1 = fmaxf(mx1, __shfl_xor_sync(0xffffffffu, mx1, 1));
        mx1 = fmaxf(mx1, __shfl_xor_sync(0xffffffffu, mx1, 2));

        float mn0 = fmaxf(m0, mx0), mn1 = fmaxf(m1, mx1);
        float corr0 = __expf(m0 - mn0), corr1 = __expf(m1 - mn1);
        float rs0 = 0.f, rs1 = 0.f;
#pragma unroll
        for (int nt = 0; nt < 8; nt++) {
            s[nt][0] = __expf(s[nt][0] - mn0);
            s[nt][1] = __expf(s[nt][1] - mn0);
            s[nt][2] = __expf(s[nt][2] - mn1);
            s[nt][3] = __expf(s[nt][3] - mn1);
            rs0 += s[nt][0] + s[nt][1];
            rs1 += s[nt][2] + s[nt][3];
        }
        rs0 += __shfl_xor_sync(0xffffffffu, rs0, 1);
        rs0 += __shfl_xor_sync(0xffffffffu, rs0, 2);
        rs1 += __shfl_xor_sync(0xffffffffu, rs1, 1);
        rs1 += __shfl_xor_sync(0xffffffffu, rs1, 2);
        l0 = l0 * corr0 + rs0;  m0 = mn0;
        l1 = l1 * corr1 + rs1;  m1 = mn1;

#pragma unroll
        for (int nt = 0; nt < 8; nt++) {
            o[nt][0] *= corr0; o[nt][1] *= corr0;
            o[nt][2] *= corr1; o[nt][3] *= corr1;
        }

        // ---- P -> smem (warp-private rows, tf32-rounded) ----
        {
            const int pr = warp * 16 + g;
#pragma unroll
            for (int nt = 0; nt < 8; nt++) {
                sP[pr * FST + nt * 8 + 2 * t    ] = tf32r(s[nt][0]);
                sP[pr * FST + nt * 8 + 2 * t + 1] = tf32r(s[nt][1]);
                sP[(pr + 8) * FST + nt * 8 + 2 * t    ] = tf32r(s[nt][2]);
                sP[(pr + 8) * FST + nt * 8 + 2 * t + 1] = tf32r(s[nt][3]);
            }
        }
        __syncwarp();

        // ---- O += P V ----
#pragma unroll
        for (int kc = 0; kc < 8; kc++) {
            float pa[4];
            pa[0] = sP[(warp * 16 + g    ) * FST + kc * 8 + t];
            pa[1] = sP[(warp * 16 + g + 8) * FST + kc * 8 + t];
            pa[2] = sP[(warp * 16 + g    ) * FST + kc * 8 + t + 4];
            pa[3] = sP[(warp * 16 + g + 8) * FST + kc * 8 + t + 4];
#pragma unroll
            for (int nt = 0; nt < 8; nt++) {
                float b0 = sV[(kc * 8 + t    ) * FST + nt * 8 + g];
                float b1 = sV[(kc * 8 + t + 4) * FST + nt * 8 + g];
                mma_tf32(o[nt], pa, b0, b1);
            }
        }
        __syncthreads();   // protect sK/sV before next iteration's loads
    }

    // ---- normalize + write ----
    float inv0 = 1.0f / l0, inv1 = 1.0f / l1;
#pragma unroll
    for (int nt = 0; nt < 8; nt++) {
        int col = headOff + nt * 8 + 2 * t;
        *(float2*)&g_o[(baseRow + row0) * Dm + col] =
            make_float2(o[nt][0] * inv0, o[nt][1] * inv0);
        *(float2*)&g_o[(baseRow + row1) * Dm + col] =
            make_float2(o[nt][2] * inv1, o[nt][3] * inv1);
    }
}

// ---------------------------------------------------------------------------
// Launch
// ---------------------------------------------------------------------------
extern "C" void kernel_launch(void* const* d_in, const int* in_sizes, int n_in,
                              void* d_out, int out_size)
{
    const float* x    = (const float*)d_in[0];
    // d_in[1] = attn_mask (statically causal triu(k=1) -> implemented directly)
    const float* wq_w = (const float*)d_in[2];
    const float* wq_A = (const float*)d_in[3];
    const float* wq_B = (const float*)d_in[4];
    const float* wk_w = (const float*)d_in[5];
    const float* wv_w = (const float*)d_in[6];
    const float* wv_A = (const float*)d_in[7];
    const float* wv_B = (const float*)d_in[8];
    const float* wo_w = (const float*)d_in[9];
    float* out = (float*)d_out;

    // 1) LoRA fold
    eff_weight_kernel<<<dim3((Dm * Dm) / 256, 1, 2), 256>>>(wq_w, wq_A, wq_B,
                                                            wv_w, wv_A, wv_B);
    // 2) Q/K/V projections (tf32 tensor cores)
    qkv_gemm_kernel<<<dim3(8, 32, 3), 256>>>(x, wk_w);

    // 3) Flash attention (tf32 tensor cores)
    int smem_bytes = 3 * 64 * FST * (int)sizeof(float);   // 52224 B
    cudaFuncSetAttribute(flash_tf32_kernel,
                         cudaFuncAttributeMaxDynamicSharedMemorySize, smem_bytes);
    flash_tf32_kernel<<<dim3(Tm / 64, Bbm * Hm), 128, smem_bytes>>>();

    // 4) Output projection -> d_out
    out_gemm_kernel<<<dim3(8, 32, 1), 256>>>(wo_w, out);
}

// round 7
// speedup vs baseline: 3.0073x; 1.0270x over previous
#include <cuda_runtime.h>
#include <math.h>
#include <stdint.h>

// Problem constants
#define Dm   1024
#define Tm   2048
#define Bbm  2
#define Hm   16
#define DHm  64
#define Rm   8
#define Mtot (Bbm * Tm)   // 4096 rows

// ---------------------------------------------------------------------------
// Scratch (device globals — no allocation allowed)
// ---------------------------------------------------------------------------
__device__ float g_wq_eff[Dm * Dm];
__device__ float g_wv_eff[Dm * Dm];
__device__ float g_wk_r[Dm * Dm];
__device__ float g_wo_r[Dm * Dm];
__device__ float g_xr[Mtot * Dm];
__device__ float g_q[Mtot * Dm];
__device__ float g_k[Mtot * Dm];
__device__ float g_v[Mtot * Dm];
__device__ float g_o[Mtot * Dm];

// ---------------------------------------------------------------------------
// tf32 / cp.async helpers
// ---------------------------------------------------------------------------
__device__ __forceinline__ float tf32r(float x) {
    uint32_t y;
    asm("cvt.rna.tf32.f32 %0, %1;" : "=r"(y) : "f"(x));
    return __uint_as_float(y);
}

__device__ __forceinline__ void cp16(void* smem, const void* g) {
    uint32_t s = (uint32_t)__cvta_generic_to_shared(smem);
    asm volatile("cp.async.cg.shared.global [%0], [%1], 16;" :: "r"(s), "l"(g) : "memory");
}
__device__ __forceinline__ void cp_commit() {
    asm volatile("cp.async.commit_group;" ::: "memory");
}
__device__ __forceinline__ void cp_wait_all() {
    asm volatile("cp.async.wait_group 0;" ::: "memory");
}

// D += A*B, m16n8k8 tf32, A row-major, B col-major, fp32 accumulate
__device__ __forceinline__ void mma_tf32(float* c, const float* a, float b0f, float b1f) {
    uint32_t a0 = __float_as_uint(a[0]);
    uint32_t a1 = __float_as_uint(a[1]);
    uint32_t a2 = __float_as_uint(a[2]);
    uint32_t a3 = __float_as_uint(a[3]);
    uint32_t b0 = __float_as_uint(b0f);
    uint32_t b1 = __float_as_uint(b1f);
    asm volatile(
        "mma.sync.aligned.m16n8k8.row.col.f32.tf32.tf32.f32 "
        "{%0,%1,%2,%3}, {%4,%5,%6,%7}, {%8,%9}, {%0,%1,%2,%3};\n"
        : "+f"(c[0]), "+f"(c[1]), "+f"(c[2]), "+f"(c[3])
        : "r"(a0), "r"(a1), "r"(a2), "r"(a3), "r"(b0), "r"(b1));
}

// ---------------------------------------------------------------------------
// 0) tf32-round a tensor elementwise (src -> dst)
// ---------------------------------------------------------------------------
__global__ __launch_bounds__(256) void round_kernel(const float* __restrict__ src,
                                                    float* __restrict__ dst, int n)
{
    int idx = (blockIdx.x * 256 + threadIdx.x) * 4;
    if (idx < n) {
        float4 v = *(const float4*)(src + idx);
        v.x = tf32r(v.x); v.y = tf32r(v.y); v.z = tf32r(v.z); v.w = tf32r(v.w);
        *(float4*)(dst + idx) = v;
    }
}

// ---------------------------------------------------------------------------
// 1) Fold LoRA into effective weights (tf32-rounded output):
//    W_eff[i,k] = round(w[i,k] + 2 * sum_r B[i,r]*A[r,k])
// ---------------------------------------------------------------------------
__global__ __launch_bounds__(256) void eff_weight_kernel(
    const float* __restrict__ wq_w, const float* __restrict__ wq_A, const float* __restrict__ wq_B,
    const float* __restrict__ wv_w, const float* __restrict__ wv_A, const float* __restrict__ wv_B)
{
    const float* w; const float* A; const float* Bp; float* out;
    if (blockIdx.z == 0) { w = wq_w; A = wq_A; Bp = wq_B; out = g_wq_eff; }
    else                 { w = wv_w; A = wv_A; Bp = wv_B; out = g_wv_eff; }
    int idx = blockIdx.x * 256 + threadIdx.x;     // over Dm*Dm
    int i = idx >> 10;
    int j = idx & 1023;
    float acc = 0.f;
#pragma unroll
    for (int r = 0; r < Rm; r++) acc += Bp[i * Rm + r] * A[r * Dm + j];
    out[idx] = tf32r(w[idx] + 2.0f * acc);
}

// ---------------------------------------------------------------------------
// tf32 tensor-core GEMM: C[M,1024] = A[M,1024] @ W[1024,1024]^T
// Inputs MUST be pre-rounded to tf32. 128x128 tile, BK=16, 256 thr = 8 warps.
// 2-stage cp.async double buffering. smem stride 20 floats (80B, 16B-aligned,
// conflict-free fragment reads).
// ---------------------------------------------------------------------------
#define GST 20

template<bool ROUND_OUT>
__device__ __forceinline__ void gemm_tf32_core(
    const float* __restrict__ A, const float* __restrict__ W, float* __restrict__ C)
{
    __shared__ float As[2][128][GST];
    __shared__ float Bs[2][128][GST];

    const int tid  = threadIdx.x;
    const int warp = tid >> 5, lane = tid & 31;
    const int g = lane >> 2, t = lane & 3;
    const int wm = warp & 1;       // 0..1  -> 64 rows each
    const int wn = warp >> 1;      // 0..3  -> 32 cols each
    const int rowBlock = blockIdx.y * 128;
    const int colBlock = blockIdx.x * 128;

    const int lr = tid >> 2;            // 0..63
    const int lc = (tid & 3) << 2;      // 0,4,8,12
    const float* Ap = A + (size_t)(rowBlock + lr) * 1024 + lc;
    const float* Wp = W + (size_t)(colBlock + lr) * 1024 + lc;

    float acc[4][4][4];
#pragma unroll
    for (int i = 0; i < 4; i++)
#pragma unroll
        for (int j = 0; j < 4; j++)
#pragma unroll
            for (int r = 0; r < 4; r++) acc[i][j][r] = 0.f;

    // preload stage 0
    cp16(&As[0][lr][lc],      Ap);
    cp16(&As[0][lr + 64][lc], Ap + (size_t)64 * 1024);
    cp16(&Bs[0][lr][lc],      Wp);
    cp16(&Bs[0][lr + 64][lc], Wp + (size_t)64 * 1024);
    cp_commit();

    for (int it = 0; it < 64; it++) {
        const int buf = it & 1;
        cp_wait_all();
        __syncthreads();

        if (it + 1 < 64) {
            const int kn = (it + 1) * 16;
            cp16(&As[buf ^ 1][lr][lc],      Ap + kn);
            cp16(&As[buf ^ 1][lr + 64][lc], Ap + (size_t)64 * 1024 + kn);
            cp16(&Bs[buf ^ 1][lr][lc],      Wp + kn);
            cp16(&Bs[buf ^ 1][lr + 64][lc], Wp + (size_t)64 * 1024 + kn);
            cp_commit();
        }

#pragma unroll
        for (int kc = 0; kc < 16; kc += 8) {
            float a[4][4];
#pragma unroll
            for (int mt = 0; mt < 4; mt++) {
                int row = wm * 64 + mt * 16;
                a[mt][0] = As[buf][row + g    ][kc + t];
                a[mt][1] = As[buf][row + g + 8][kc + t];
                a[mt][2] = As[buf][row + g    ][kc + t + 4];
                a[mt][3] = As[buf][row + g + 8][kc + t + 4];
            }
            float b[4][2];
#pragma unroll
            for (int nt = 0; nt < 4; nt++) {
                int col = wn * 32 + nt * 8;
                b[nt][0] = Bs[buf][col + g][kc + t];
                b[nt][1] = Bs[buf][col + g][kc + t + 4];
            }
#pragma unroll
            for (int mt = 0; mt < 4; mt++)
#pragma unroll
                for (int nt = 0; nt < 4; nt++)
                    mma_tf32(acc[mt][nt], a[mt], b[nt][0], b[nt][1]);
        }
        __syncthreads();
    }

    // epilogue: c0,c1 at (row g, cols 2t,2t+1); c2,c3 at row g+8
#pragma unroll
    for (int mt = 0; mt < 4; mt++) {
        int row = rowBlock + wm * 64 + mt * 16 + g;
#pragma unroll
        for (int nt = 0; nt < 4; nt++) {
            int col = colBlock + wn * 32 + nt * 8 + 2 * t;
            float c0 = acc[mt][nt][0], c1 = acc[mt][nt][1];
            float c2 = acc[mt][nt][2], c3 = acc[mt][nt][3];
            if (ROUND_OUT) { c0 = tf32r(c0); c1 = tf32r(c1); c2 = tf32r(c2); c3 = tf32r(c3); }
            *(float2*)&C[(size_t)row * 1024 + col]       = make_float2(c0, c1);
            *(float2*)&C[(size_t)(row + 8) * 1024 + col] = make_float2(c2, c3);
        }
    }
}

// 2) Q/K/V projections fused over grid.z (outputs tf32-rounded for flash)
__global__ __launch_bounds__(256) void qkv_gemm_kernel()
{
    const float* W; float* C;
    if (blockIdx.z == 0)      { W = g_wq_eff; C = g_q; }
    else if (blockIdx.z == 1) { W = g_wk_r;   C = g_k; }
    else                      { W = g_wv_eff; C = g_v; }
    gemm_tf32_core<true>(g_xr, W, C);
}

// 4) Output projection: out = attn_out @ wo^T (full-precision output)
__global__ __launch_bounds__(256) void out_gemm_kernel(float* __restrict__ out)
{
    gemm_tf32_core<false>(g_o, g_wo_r, out);
}

// ---------------------------------------------------------------------------
// 3) Causal flash attention, tensor-core tf32, cp.async double-buffered K/V.
//    Block = 64 queries x one (b,h). 128 threads = 4 warps, warp = 16 q-rows.
//    Q/K/V are pre-rounded tf32 (producer epilogues), so loads are raw copies.
// ---------------------------------------------------------------------------
#define FST 68

__global__ __launch_bounds__(128) void flash_tf32_kernel()
{
    extern __shared__ float sh[];
    float* sK0 = sh;                    // [64][FST]
    float* sK1 = sh + 64 * FST;
    float* sV0 = sh + 2 * 64 * FST;
    float* sV1 = sh + 3 * 64 * FST;
    float* sP  = sh + 4 * 64 * FST;     // [64][FST] (Q staging, then P bands)

    const int tid  = threadIdx.x;
    const int warp = tid >> 5, lane = tid & 31;
    const int g = lane >> 2, t = lane & 3;
    const int bh = blockIdx.y;             // 0..31
    const int b = bh >> 4, h = bh & 15;
    const int qt = gridDim.x - 1 - blockIdx.x;   // longest tiles first
    const int q0 = qt * 64;
    const size_t baseRow = (size_t)b * Tm;
    const int headOff = h * DHm;

    // ---- kick off K/V tile 0 loads, stage Q via sP, extract A-fragments ----
#pragma unroll
    for (int i = tid; i < 64 * 16; i += 128) {
        int r = i >> 4, c4 = (i & 15) << 2;
        size_t gidx = (baseRow + r) * Dm + headOff + c4;   // k0 = 0
        cp16(&sK0[r * FST + c4], &g_k[gidx]);
        cp16(&sV0[r * FST + c4], &g_v[gidx]);
    }
    cp_commit();

    for (int i = tid; i < 64 * 16; i += 128) {
        int r = i >> 4, c4 = (i & 15) << 2;
        *(float4*)&sP[r * FST + c4] =
            *(const float4*)&g_q[(baseRow + q0 + r) * Dm + headOff + c4];
    }
    __syncthreads();
    float qf[8][4];
    {
        const int rb = warp * 16;
#pragma unroll
        for (int kc = 0; kc < 8; kc++) {
            qf[kc][0] = sP[(rb + g    ) * FST + kc * 8 + t];
            qf[kc][1] = sP[(rb + g + 8) * FST + kc * 8 + t];
            qf[kc][2] = sP[(rb + g    ) * FST + kc * 8 + t + 4];
            qf[kc][3] = sP[(rb + g + 8) * FST + kc * 8 + t + 4];
        }
    }
    __syncthreads();

    float m0 = -1e30f, m1 = -1e30f, l0 = 0.f, l1 = 0.f;
    float o[8][4];
#pragma unroll
    for (int nt = 0; nt < 8; nt++)
#pragma unroll
        for (int r = 0; r < 4; r++) o[nt][r] = 0.f;

    const int row0 = q0 + warp * 16 + g;
    const int row1 = row0 + 8;

    for (int kt = 0; kt <= qt; kt++) {
        const int buf = kt & 1;
        float* sK = buf ? sK1 : sK0;
        float* sV = buf ? sV1 : sV0;

        cp_wait_all();
        __syncthreads();

        if (kt < qt) {   // prefetch next K/V tile into other buffer
            float* nK = buf ? sK0 : sK1;
            float* nV = buf ? sV0 : sV1;
            const int kn = (kt + 1) * 64;
            for (int i = tid; i < 64 * 16; i += 128) {
                int r = i >> 4, c4 = (i & 15) << 2;
                size_t gidx = (baseRow + kn + r) * Dm + headOff + c4;
                cp16(&nK[r * FST + c4], &g_k[gidx]);
                cp16(&nV[r * FST + c4], &g_v[gidx]);
            }
            cp_commit();
        }

        // ---- S = Q K^T ----
        const int k0 = kt * 64;
        float s[8][4];
#pragma unroll
        for (int nt = 0; nt < 8; nt++) {
            s[nt][0] = s[nt][1] = s[nt][2] = s[nt][3] = 0.f;
#pragma unroll
            for (int kc = 0; kc < 8; kc++) {
                float b0 = sK[(nt * 8 + g) * FST + kc * 8 + t];
                float b1 = sK[(nt * 8 + g) * FST + kc * 8 + t + 4];
                mma_tf32(s[nt], qf[kc], b0, b1);
            }
        }

        // ---- scale + causal mask ----
        const bool diag = (kt == qt);
#pragma unroll
        for (int nt = 0; nt < 8; nt++) {
            int c0 = k0 + nt * 8 + 2 * t, c1 = c0 + 1;
            s[nt][0] *= 0.125f; s[nt][1] *= 0.125f;
            s[nt][2] *= 0.125f; s[nt][3] *= 0.125f;
            if (diag) {
                if (c0 > row0) s[nt][0] = -1e30f;
                if (c1 > row0) s[nt][1] = -1e30f;
                if (c0 > row1) s[nt][2] = -1e30f;
                if (c1 > row1) s[nt][3] = -1e30f;
            }
        }

        // ---- online softmax (rows row0,row1; quad reduce = xor1, xor2) ----
        float mx0 = -1e30f, mx1 = -1e30f;
#pragma unroll
        for (int nt = 0; nt < 8; nt++) {
            mx0 = fmaxf(mx0, fmaxf(s[nt][0], s[nt][1]));
            mx1 = fmaxf(mx1, fmaxf(s[nt][2], s[nt][3]));
        }
        mx0 = fmaxf(mx0, __shfl_xor_sync(0xffffffffu, mx0, 1));
        mx0 = fmaxf(mx0, __shfl_xor_sync(0xffffffffu, mx0, 2));
        mx1 = fmaxf(mx1, __shfl_xor_sync(0xffffffffu, mx1, 1));
        mx1 = fmaxf(mx1, __shfl_xor_sync(0xffffffffu, mx1, 2));

        float mn0 = fmaxf(m0, mx0), mn1 = fmaxf(m1, mx1);
        float corr0 = __expf(m0 - mn0), corr1 = __expf(m1 - mn1);
        float rs0 = 0.f, rs1 = 0.f;
#pragma unroll
        for (int nt = 0; nt < 8; nt++) {
            s[nt][0] = __expf(s[nt][0] - mn0);
            s[nt][1] = __expf(s[nt][1] - mn0);
            s[nt][2] = __expf(s[nt][2] - mn1);
            s[nt][3] = __expf(s[nt][3] - mn1);
            rs0 += s[nt][0] + s[nt][1];
            rs1 += s[nt][2] + s[nt][3];
        }
        rs0 += __shfl_xor_sync(0xffffffffu, rs0, 1);
        rs0 += __shfl_xor_sync(0xffffffffu, rs0, 2);
        rs1 += __shfl_xor_sync(0xffffffffu, rs1, 1);
        rs1 += __shfl_xor_sync(0xffffffffu, rs1, 2);
        l0 = l0 * corr0 + rs0;  m0 = mn0;
        l1 = l1 * corr1 + rs1;  m1 = mn1;

#pragma unroll
        for (int nt = 0; nt < 8; nt++) {
            o[nt][0] *= corr0; o[nt][1] *= corr0;
            o[nt][2] *= corr1; o[nt][3] *= corr1;
        }

        // ---- P -> smem (warp-private 16-row band, tf32-rounded) ----
        {
            const int pr = warp * 16 + g;
#pragma unroll
            for (int nt = 0; nt < 8; nt++) {
                sP[pr * FST + nt * 8 + 2 * t    ]       = tf32r(s[nt][0]);
                sP[pr * FST + nt * 8 + 2 * t + 1]       = tf32r(s[nt][1]);
                sP[(pr + 8) * FST + nt * 8 + 2 * t    ] = tf32r(s[nt][2]);
                sP[(pr + 8) * FST + nt * 8 + 2 * t + 1] = tf32r(s[nt][3]);
            }
        }
        __syncwarp();

        // ---- O += P V ----
#pragma unroll
        for (int kc = 0; kc < 8; kc++) {
            float pa[4];
            pa[0] = sP[(warp * 16 + g    ) * FST + kc * 8 + t];
            pa[1] = sP[(warp * 16 + g + 8) * FST + kc * 8 + t];
            pa[2] = sP[(warp * 16 + g    ) * FST + kc * 8 + t + 4];
            pa[3] = sP[(warp * 16 + g + 8) * FST + kc * 8 + t + 4];
#pragma unroll
            for (int nt = 0; nt < 8; nt++) {
                float b0 = sV[(kc * 8 + t    ) * FST + nt * 8 + g];
                float b1 = sV[(kc * 8 + t + 4) * FST + nt * 8 + g];
                mma_tf32(o[nt], pa, b0, b1);
            }
        }
        __syncthreads();   // all reads of sK/sV done before prefetch overwrite
    }

    // ---- normalize + write (tf32-rounded for the wo GEMM) ----
    float inv0 = 1.0f / l0, inv1 = 1.0f / l1;
#pragma unroll
    for (int nt = 0; nt < 8; nt++) {
        int col = headOff + nt * 8 + 2 * t;
        *(float2*)&g_o[(baseRow + row0) * Dm + col] =
            make_float2(tf32r(o[nt][0] * inv0), tf32r(o[nt][1] * inv0));
        *(float2*)&g_o[(baseRow + row1) * Dm + col] =
            make_float2(tf32r(o[nt][2] * inv1), tf32r(o[nt][3] * inv1));
    }
}

// ---------------------------------------------------------------------------
// Launch
// ---------------------------------------------------------------------------
extern "C" void kernel_launch(void* const* d_in, const int* in_sizes, int n_in,
                              void* d_out, int out_size)
{
    const float* x    = (const float*)d_in[0];
    // d_in[1] = attn_mask (statically causal triu(k=1) -> implemented directly)
    const float* wq_w = (const float*)d_in[2];
    const float* wq_A = (const float*)d_in[3];
    const float* wq_B = (const float*)d_in[4];
    const float* wk_w = (const float*)d_in[5];
    const float* wv_w = (const float*)d_in[6];
    const float* wv_A = (const float*)d_in[7];
    const float* wv_B = (const float*)d_in[8];
    const float* wo_w = (const float*)d_in[9];
    float* out = (float*)d_out;

    float* xr;   cudaGetSymbolAddress((void**)&xr,   g_xr);
    float* wkr;  cudaGetSymbolAddress((void**)&wkr,  g_wk_r);
    float* wor;  cudaGetSymbolAddress((void**)&wor,  g_wo_r);

    // 0) pre-round inputs to tf32 (enables raw cp.async everywhere)
    round_kernel<<<(Mtot * Dm / 4 + 255) / 256, 256>>>(x, xr, Mtot * Dm);
    round_kernel<<<(Dm * Dm / 4 + 255) / 256, 256>>>(wk_w, wkr, Dm * Dm);
    round_kernel<<<(Dm * Dm / 4 + 255) / 256, 256>>>(wo_w, wor, Dm * Dm);

    // 1) LoRA fold (tf32-rounded)
    eff_weight_kernel<<<dim3((Dm * Dm) / 256, 1, 2), 256>>>(wq_w, wq_A, wq_B,
                                                            wv_w, wv_A, wv_B);
    // 2) Q/K/V projections (tf32 tensor cores, cp.async pipelined)
    qkv_gemm_kernel<<<dim3(8, 32, 3), 256>>>();

    // 3) Flash attention (tf32 tensor cores, cp.async double-buffered K/V)
    int smem_bytes = 5 * 64 * FST * (int)sizeof(float);   // 87040 B
    cudaFuncSetAttribute(flash_tf32_kernel,
                         cudaFuncAttributeMaxDynamicSharedMemorySize, smem_bytes);
    flash_tf32_kernel<<<dim3(Tm / 64, Bbm * Hm), 128, smem_bytes>>>();

    // 4) Output projection -> d_out
    out_gemm_kernel<<<dim3(8, 32, 1), 256>>>(out);
}